// round 17
// baseline (speedup 1.0000x reference)
#include <cuda_runtime.h>
#include <cuda_bf16.h>
#include <cstdint>

#define NN 10000
#define EE 160000
#define CC 128
#define DD 512
#define HH 64
#define W4C 640
#define HT 130   // padded stride for transposed h tiles [k][e]

#define INV_SQRT3 0.57735026918962576f
#define INV_SQRT2 0.70710678118654752f
#define LIN_SCALE 0.088388347648318447f   // 1/sqrt(128)

// Scratch (device globals; no runtime alloc)
// g_agg layout: [node][channel c (128)][4] where 4 = (m0, m1x, m1y, m1z)
__device__ float g_agg[(size_t)NN * DD];
__device__ uint4 g_b4[4 * 80 * 32];            // Wm4 split B-frags
__device__ uint4 g_ob4[2 * 16 * 16 * 32];      // out weights split B-frags (K=256)
__device__ uint4 g_b23[2 * 4 * 8 * 32];        // Wm2/Wm3 split B-frags

typedef unsigned long long u64;

__device__ __forceinline__ float silu_f(float x) { return x / (1.0f + __expf(-x)); }

__device__ __forceinline__ uint32_t pack_bf16(__nv_bfloat16 first, __nv_bfloat16 second) {
    return (uint32_t)__bfloat16_as_ushort(first) | ((uint32_t)__bfloat16_as_ushort(second) << 16);
}
__device__ __forceinline__ void split_pack(float x, float y, uint32_t& hi, uint32_t& lo) {
    const __nv_bfloat16 bx = __float2bfloat16(x);
    const __nv_bfloat16 by = __float2bfloat16(y);
    const __nv_bfloat16 rx = __float2bfloat16(x - __bfloat162float(bx));
    const __nv_bfloat16 ry = __float2bfloat16(y - __bfloat162float(by));
    hi = pack_bf16(bx, by);
    lo = pack_bf16(rx, ry);
}

__device__ __forceinline__ void mma_bf16(float* c, const uint32_t* a, uint32_t b0, uint32_t b1) {
    asm volatile("mma.sync.aligned.m16n8k16.row.col.f32.bf16.bf16.f32 "
        "{%0,%1,%2,%3}, {%4,%5,%6,%7}, {%8,%9}, {%0,%1,%2,%3};"
        : "+f"(c[0]), "+f"(c[1]), "+f"(c[2]), "+f"(c[3])
        : "r"(a[0]), "r"(a[1]), "r"(a[2]), "r"(a[3]), "r"(b0), "r"(b1));
}

// ---------------------------------------------------------------------------
// prep (single launch): zero agg + split Wm4 + Wm2/3 + out weights.
// Block ranges: [0,40) b4 | [40,48) b23 | [48,112) ow | [112,5112) zero.
// ---------------------------------------------------------------------------
#define PREP_B4_BLKS  40
#define PREP_B23_BLKS 8
#define PREP_OW_BLKS  64
#define PREP_WORK_BLKS (PREP_B4_BLKS + PREP_B23_BLKS + PREP_OW_BLKS)   // 112
#define ZERO_BLKS ((NN * DD) / (256 * 4))                               // 5000
#define PREP_TOTAL_BLKS (PREP_WORK_BLKS + ZERO_BLKS)

__global__ void __launch_bounds__(256)
prep_kernel(const float* __restrict__ Wm4,
            const float* __restrict__ Wm2, const float* __restrict__ Wm3,
            const float* __restrict__ rW0, const float* __restrict__ rW1,
            const float* __restrict__ skW0, const float* __restrict__ skW1)
{
    const int b = blockIdx.x;
    if (b >= PREP_WORK_BLKS) {
        const size_t i = (size_t)(b - PREP_WORK_BLKS) * 256 + threadIdx.x;
        ((float4*)g_agg)[i] = make_float4(0.f, 0.f, 0.f, 0.f);
        return;
    }
    if (b < PREP_B4_BLKS) {
        const int tid = b * 256 + threadIdx.x;
        if (tid >= 4 * 80 * 32) return;
        const int lane = tid & 31;
        const int idx = tid >> 5;
        const int kt = idx / 80, nt = idx % 80;
        const int g = lane >> 2, t = lane & 3;
        const int n = nt * 8 + g;
        const int k0 = kt * 16 + 2 * t;
        uint4 o;
        split_pack(Wm4[k0 * W4C + n],       Wm4[(k0 + 1) * W4C + n], o.x, o.z);
        split_pack(Wm4[(k0 + 8) * W4C + n], Wm4[(k0 + 9) * W4C + n], o.y, o.w);
        g_b4[idx * 32 + lane] = o;
        return;
    }
    if (b < PREP_B4_BLKS + PREP_B23_BLKS) {
        const int tid = (b - PREP_B4_BLKS) * 256 + threadIdx.x;
        if (tid >= 2 * 4 * 8 * 32) return;
        const int lane = tid & 31;
        const int idx = tid >> 5;           // layer*32 + kt*8 + nt
        const int layer = idx >> 5;
        const int kt = (idx >> 3) & 3;
        const int nt = idx & 7;
        const int g = lane >> 2, t = lane & 3;
        const int n = nt * 8 + g;
        const int k0 = kt * 16 + 2 * t;
        const float* W = layer ? Wm3 : Wm2;
        uint4 o;
        split_pack(W[k0 * HH + n],       W[(k0 + 1) * HH + n], o.x, o.z);
        split_pack(W[(k0 + 8) * HH + n], W[(k0 + 9) * HH + n], o.y, o.w);
        g_b23[idx * 32 + lane] = o;
        return;
    }
    {
        const int tid = (b - PREP_B4_BLKS - PREP_B23_BLKS) * 256 + threadIdx.x;
        if (tid >= 2 * 16 * 16 * 32) return;
        const int lane = tid & 31;
        const int idx = tid >> 5;           // s*256 + kt*16 + nt
        const int s = idx >> 8;
        const int kt = (idx >> 4) & 15;
        const int nt = idx & 15;
        const int g = lane >> 2, t = lane & 3;
        const int n = nt * 8 + g;
        const float* Wa = s ? rW1 : rW0;
        const float* Wb = s ? skW1 : skW0;
        float v[4];
#pragma unroll
        for (int q = 0; q < 4; ++q) {
            const int k = kt * 16 + 2 * t + (q & 1) + (q >> 1) * 8;
            v[q] = (k < 128) ? Wa[k * CC + n] : Wb[(k - 128) * CC + n];
        }
        uint4 o;
        split_pack(v[0], v[1], o.x, o.z);
        split_pack(v[2], v[3], o.y, o.w);
        g_ob4[idx * 32 + lane] = o;
    }
}

// ---------------------------------------------------------------------------
// HMMA 64->64 layer (3-term bf16 split) + silu; transposed smem in/out.
// ---------------------------------------------------------------------------
__device__ __forceinline__ void layer_hmma(const uint4* __restrict__ gB,
                                           const float* sIn, float* sOut,
                                           int w, int lane)
{
    const int g = lane >> 2, t = lane & 3;
    const int er = w * 16 + g;

    float acc[8][4];
#pragma unroll
    for (int nt = 0; nt < 8; ++nt)
#pragma unroll
        for (int i = 0; i < 4; ++i) acc[nt][i] = 0.f;

#pragma unroll
    for (int kt = 0; kt < 4; ++kt) {
        const int k0 = kt * 16 + 2 * t;
        const float* b0 = sIn + (k0)     * HT;
        const float* b1 = sIn + (k0 + 1) * HT;
        const float* b8 = sIn + (k0 + 8) * HT;
        const float* b9 = sIn + (k0 + 9) * HT;
        uint32_t Ah[4], Al[4];
        split_pack(b0[er],     b1[er],     Ah[0], Al[0]);
        split_pack(b0[er + 8], b1[er + 8], Ah[1], Al[1]);
        split_pack(b8[er],     b9[er],     Ah[2], Al[2]);
        split_pack(b8[er + 8], b9[er + 8], Ah[3], Al[3]);

#pragma unroll
        for (int nt = 0; nt < 8; ++nt) {
            const uint4 bb = __ldg(gB + (kt * 8 + nt) * 32 + lane);
            mma_bf16(acc[nt], Ah, bb.x, bb.y);
            mma_bf16(acc[nt], Al, bb.x, bb.y);
            mma_bf16(acc[nt], Ah, bb.z, bb.w);
        }
    }

#pragma unroll
    for (int nt = 0; nt < 8; ++nt) {
        const int c0 = nt * 8 + 2 * t;
        sOut[(c0)     * HT + er]     = silu_f(acc[nt][0]);
        sOut[(c0 + 1) * HT + er]     = silu_f(acc[nt][1]);
        sOut[(c0)     * HT + er + 8] = silu_f(acc[nt][2]);
        sOut[(c0 + 1) * HT + er + 8] = silu_f(acc[nt][3]);
    }
}

// ---------------------------------------------------------------------------
// MEGA kernel: MLP (layers 1-3) + GEMM4 + messages + scatter per 128 edges.
// A-fragments stay in registers (no global round-trip). s_y aliases sHb.
// dyn smem: sE 1024 | sW1 512 | sHa 8320 | sHb 8320  = 72704 B
// ---------------------------------------------------------------------------
__global__ void __launch_bounds__(256, 2)
edge_kernel(const float* __restrict__ emb, const float* __restrict__ Wm1,
            const float* __restrict__ nf, const float* __restrict__ ef,
            const float* __restrict__ attrs,
            const int* __restrict__ snd, const int* __restrict__ rcv)
{
    extern __shared__ float sm[];
    float* sE  = sm;
    float* sW1 = sm + 1024;
    float* sHa = sm + 1536;
    float* sHb = sm + 1536 + HH * HT;
    float4* s_y = (float4*)sHb;            // [8][160] float4, aliased after layer 3
    __shared__ int s_snd[8][16];
    __shared__ int s_rcv[8][16];

    const int tid  = threadIdx.x;
    const int w    = tid >> 5;
    const int lane = tid & 31;
    const size_t e0 = (size_t)blockIdx.x * 128;

    // ---- stage inputs ----
    for (int i = tid; i < 1024; i += 256) sE[i] = emb[e0 * 8 + i];
    for (int i = tid; i < 512; i += 256)  sW1[i] = Wm1[i];
    if (lane < 16) {
        s_snd[w][lane] = snd[e0 + (size_t)(w * 16 + lane)];
        s_rcv[w][lane] = rcv[e0 + (size_t)(w * 16 + lane)];
    }
    __syncthreads();

    // ---- layer 1 (scalar, K=8) ----
    {
        const int jq = tid & 15;
        const int eg = tid >> 4;
        const int jbase = jq * 4;
        const int ebase = eg * 8;
        float wv[8][4];
#pragma unroll
        for (int r = 0; r < 8; ++r) {
            const float4 w4 = *(const float4*)(sW1 + r * HH + jbase);
            wv[r][0] = w4.x; wv[r][1] = w4.y; wv[r][2] = w4.z; wv[r][3] = w4.w;
        }
#pragma unroll
        for (int e = 0; e < 8; ++e) {
            const float4 ea = *(const float4*)(sE + (ebase + e) * 8);
            const float4 eb = *(const float4*)(sE + (ebase + e) * 8 + 4);
            const float er8[8] = {ea.x, ea.y, ea.z, ea.w, eb.x, eb.y, eb.z, eb.w};
#pragma unroll
            for (int c = 0; c < 4; ++c) {
                float acc = 0.f;
#pragma unroll
                for (int r = 0; r < 8; ++r) acc += er8[r] * wv[r][c];
                sHa[(jbase + c) * HT + ebase + e] = silu_f(acc);
            }
        }
    }
    __syncthreads();

    // ---- layers 2-3 (HMMA) ----
    layer_hmma(g_b23,        sHa, sHb, w, lane);
    __syncthreads();
    layer_hmma(g_b23 + 1024, sHb, sHa, w, lane);
    __syncthreads();                       // all reads of sHb done -> s_y may alias

    // ---- build A fragments in registers from sHa ----
    const int gr = lane >> 2;
    const int t  = lane & 3;
    uint32_t Ah[4][4], Al[4][4];
    {
        const int er = w * 16 + gr;
#pragma unroll
        for (int kt = 0; kt < 4; ++kt) {
            const int k0 = kt * 16 + 2 * t;
            const float* b0 = sHa + (k0)     * HT;
            const float* b1 = sHa + (k0 + 1) * HT;
            const float* b8 = sHa + (k0 + 8) * HT;
            const float* b9 = sHa + (k0 + 9) * HT;
            split_pack(b0[er],     b1[er],     Ah[kt][0], Al[kt][0]);
            split_pack(b0[er + 8], b1[er + 8], Ah[kt][1], Al[kt][1]);
            split_pack(b8[er],     b9[er],     Ah[kt][2], Al[kt][2]);
            split_pack(b8[er + 8], b9[er + 8], Ah[kt][3], Al[kt][3]);
        }
    }

    // ---- message phase (R7/R11 structure, interleaved scatter) ----
    const int eml = gr + 8 * (t & 1);
    const size_t em = e0 + (size_t)(w * 16 + eml);
    const float4 sh = *(const float4*)(attrs + em * 4);
    const float sh0 = sh.x, s1x = sh.y, s1y = sh.z, s1z = sh.w;
    float* pagg = g_agg + (size_t)s_rcv[w][eml] * DD;

    const int jP = lane & 7;
    const int ch4P  = (jP < 2) ? jP : (jP - 2) / 3;
    const int slotP = (jP < 2) ? 0 : ((jP - 2) % 3) + 1;
    const int offMul = (jP < 2) ? 8 : 24;
    const int offAdd = (jP < 2) ? jP * 4 : CC + (jP - 2) * 4;
    const int elBase = lane >> 3;

    float4* myY = s_y + w * 160;

#pragma unroll 1
    for (int tile = 0; tile < 16; ++tile) {
        const int off = tile * offMul + offAdd;
        float4 xa[4], xb[4], xc[4];
#pragma unroll
        for (int it = 0; it < 4; ++it) {
            const int el = it * 4 + elBase;
            xa[it] = __ldg((const float4*)(nf + (size_t)s_snd[w][el] * DD + off));
            xb[it] = __ldg((const float4*)(nf + (size_t)s_rcv[w][el] * DD + off));
            xc[it] = __ldg((const float4*)(ef + (e0 + (size_t)(w * 16 + el)) * DD + off));
        }

        float acc[5][4];
#pragma unroll
        for (int q = 0; q < 5; ++q)
#pragma unroll
            for (int i = 0; i < 4; ++i) acc[q][i] = 0.f;

#pragma unroll
        for (int q = 0; q < 5; ++q) {
#pragma unroll
            for (int kt = 0; kt < 4; ++kt) {
                const uint4 bb = __ldg(g_b4 + ((kt * 80 + q * 16 + tile) * 32 + lane));
                mma_bf16(acc[q], Ah[kt], bb.x, bb.y);
                mma_bf16(acc[q], Al[kt], bb.x, bb.y);
                mma_bf16(acc[q], Ah[kt], bb.z, bb.w);
            }
        }

#pragma unroll
        for (int it = 0; it < 4; ++it) {
            const int el = it * 4 + elBase;
            const int c = (el & 7) * 4 + (el >> 3) + 2 * ch4P;
            myY[c * 5 + slotP] = make_float4(
                xa[it].x + xb[it].x + xc[it].x,
                xa[it].y + xb[it].y + xc[it].y,
                xa[it].z + xb[it].z + xc[it].z,
                xa[it].w + xb[it].w + xc[it].w);
        }
        __syncwarp();

        const float4* my = myY + lane * 5;
        const float4 X0 = my[0];
        const float4 V0 = my[1];
        const float4 V1 = my[2];
        const float4 V2 = my[3];
        const float x0[4]  = {X0.x, X0.y, X0.z, X0.w};
        const float xv[12] = {V0.x, V0.y, V0.z, V0.w,
                              V1.x, V1.y, V1.z, V1.w,
                              V2.x, V2.y, V2.z, V2.w};

        float accr[5][4];
#pragma unroll
        for (int q = 0; q < 5; ++q) {
#pragma unroll
            for (int i = 0; i < 4; ++i) accr[q][i] = acc[q][i];
            const float s0 = (t & 1) ? acc[q][0] : acc[q][2];
            const float s1 = (t & 1) ? acc[q][1] : acc[q][3];
            const float r0 = __shfl_xor_sync(0xffffffffu, s0, 1);
            const float r1 = __shfl_xor_sync(0xffffffffu, s1, 1);
            if (t & 1) { accr[q][0] = r0; accr[q][1] = r1; }
            else       { accr[q][2] = r0; accr[q][3] = r1; }
        }
        const int cm = tile * 8 + (t >> 1) * 4;

#pragma unroll
        for (int j = 0; j < 4; ++j) {
            const float u0 = xv[3 * j], u1 = xv[3 * j + 1], u2 = xv[3 * j + 2];
            const float dot = u0 * s1x + u1 * s1y + u2 * s1z;
            const float m0 = accr[0][j] * x0[j] * sh0 + accr[1][j] * dot * INV_SQRT3;
            const float cx = u1 * s1z - u2 * s1y;
            const float cy = u2 * s1x - u0 * s1z;
            const float cz = u0 * s1y - u1 * s1x;
            const float mx = accr[2][j] * u0 * sh0 + accr[3][j] * x0[j] * s1x + accr[4][j] * cx * INV_SQRT2;
            const float my2 = accr[2][j] * u1 * sh0 + accr[3][j] * x0[j] * s1y + accr[4][j] * cy * INV_SQRT2;
            const float mz = accr[2][j] * u2 * sh0 + accr[3][j] * x0[j] * s1z + accr[4][j] * cz * INV_SQRT2;
            asm volatile("red.global.add.v4.f32 [%0], {%1,%2,%3,%4};"
                         :: "l"(pagg + (size_t)(cm + j) * 4),
                            "f"(m0), "f"(mx), "f"(my2), "f"(mz)
                         : "memory");
        }
        __syncwarp();
    }
}

// ---------------------------------------------------------------------------
// out via tensor cores (R15, measured good). Grid (157, 4).
// ---------------------------------------------------------------------------
#define XST 260
#define OUT_SMEM (64 * XST * 4)       // 66560 B

__global__ void __launch_bounds__(256)
out_tc_kernel(const float* __restrict__ nf, float* __restrict__ out)
{
    extern __shared__ float Xs[];

    const int tid = threadIdx.x;
    const int p = blockIdx.y;
    const size_t n0 = (size_t)blockIdx.x * 64;

    for (int i = tid; i < 64 * CC; i += 256) {
        const int n = i >> 7;
        const int c = i & 127;
        float v = 0.f;
        if (n0 + n < NN) v = g_agg[(n0 + n) * DD + c * 4 + p];
        Xs[n * XST + c] = v;
    }
    for (int i = tid; i < 64 * CC; i += 256) {
        const int n = i >> 7;
        const int c = i & 127;
        float v = 0.f;
        if (n0 + n < NN) {
            const int col = (p == 0) ? c : (CC + 3 * c + (p - 1));
            v = nf[(n0 + n) * DD + col];
        }
        Xs[n * XST + 128 + c] = v;
    }
    __syncthreads();

    const int w    = tid >> 5;
    const int lane = tid & 31;
    const int mg   = w & 3;
    const int nh   = w >> 2;
    const int g = lane >> 2, t = lane & 3;
    const int rA = mg * 16 + g;
    const int s = (p == 0) ? 0 : 1;

    float acc[8][4];
#pragma unroll
    for (int nt8 = 0; nt8 < 8; ++nt8)
#pragma unroll
        for (int i = 0; i < 4; ++i) acc[nt8][i] = 0.f;

#pragma unroll 1
    for (int kt = 0; kt < 16; ++kt) {
        const int k = kt * 16 + 2 * t;
        const float* r0 = Xs + rA * XST;
        const float* r8 = Xs + (rA + 8) * XST;
        uint32_t Ah[4], Al[4];
        split_pack(r0[k],     r0[k + 1], Ah[0], Al[0]);
        split_pack(r8[k],     r8[k + 1], Ah[1], Al[1]);
        split_pack(r0[k + 8], r0[k + 9], Ah[2], Al[2]);
        split_pack(r8[k + 8], r8[k + 9], Ah[3], Al[3]);

#pragma unroll
        for (int nt8 = 0; nt8 < 8; ++nt8) {
            const int nt = nh * 8 + nt8;
            const uint4 bb = __ldg(g_ob4 + ((s * 16 + kt) * 16 + nt) * 32 + lane);
            mma_bf16(acc[nt8], Ah, bb.x, bb.y);
            mma_bf16(acc[nt8], Al, bb.x, bb.y);
            mma_bf16(acc[nt8], Ah, bb.z, bb.w);
        }
    }

#pragma unroll
    for (int nt8 = 0; nt8 < 8; ++nt8) {
        const int d0 = nh * 64 + nt8 * 8 + 2 * t;
#pragma unroll
        for (int half = 0; half < 2; ++half) {
            const int r = rA + half * 8;
            if (n0 + r >= NN) continue;
            const float v0 = Xs[r * XST + d0]     + acc[nt8][half * 2]     * LIN_SCALE;
            const float v1 = Xs[r * XST + d0 + 1] + acc[nt8][half * 2 + 1] * LIN_SCALE;
            float* ob = out + (n0 + r) * DD;
            if (p == 0) {
                *(float2*)(ob + d0) = make_float2(v0, v1);
            } else {
                ob[CC + 3 * d0 + (p - 1)]       = v0;
                ob[CC + 3 * (d0 + 1) + (p - 1)] = v1;
            }
        }
    }
}

// ---------------------------------------------------------------------------
extern "C" void kernel_launch(void* const* d_in, const int* in_sizes, int n_in,
                              void* d_out, int out_size)
{
    const float* nf    = (const float*)d_in[0];
    const float* ef    = (const float*)d_in[1];
    const float* attrs = (const float*)d_in[2];
    const float* emb   = (const float*)d_in[3];
    const int*   snd   = (const int*)d_in[4];
    const int*   rcv   = (const int*)d_in[5];
    const float* Wm1   = (const float*)d_in[6];
    const float* Wm2   = (const float*)d_in[7];
    const float* Wm3   = (const float*)d_in[8];
    const float* Wm4   = (const float*)d_in[9];
    const float* rW0   = (const float*)d_in[10];
    const float* rW1   = (const float*)d_in[11];
    const float* sW0   = (const float*)d_in[12];
    const float* sW1   = (const float*)d_in[13];
    float* out = (float*)d_out;

    const int edge_smem = (1536 + 2 * HH * HT) * 4;   // 72704 B
    static bool attr_done = false;
    if (!attr_done) {
        cudaFuncSetAttribute(edge_kernel, cudaFuncAttributeMaxDynamicSharedMemorySize, edge_smem);
        cudaFuncSetAttribute(out_tc_kernel, cudaFuncAttributeMaxDynamicSharedMemorySize, OUT_SMEM);
        attr_done = true;
    }

    prep_kernel<<<PREP_TOTAL_BLKS, 256>>>(Wm4, Wm2, Wm3, rW0, rW1, sW0, sW1);
    edge_kernel<<<EE / 128, 256, edge_smem>>>(emb, Wm1, nf, ef, attrs, snd, rcv);
    out_tc_kernel<<<dim3((NN + 63) / 64, 4), 256, OUT_SMEM>>>(nf, out);
}